// round 1
// baseline (speedup 1.0000x reference)
#include <cuda_runtime.h>
#include <cuda_bf16.h>
#include <cstdint>

// Problem constants
#define BB   8
#define FI   512
#define FO   512
#define HH   64
#define WW   64
#define KK   3
#define DSTYLE 512

#define FC_SCALE 0.04419417382415922f      // 512^-0.5
#define W_SCALE  0.014731391274719739f     // (512*9)^-0.5
#define EPSI     1e-8f

// Conv tiling
#define FO_TILE  64
#define TH       2          // output rows per block
#define FI_CHUNK 16
#define SXW      68         // padded smem row stride (floats), 272B = 17*16 -> float4 aligned
#define SX_PLANE (4*SXW)    // (TH+2) rows per fi

// Scratch (device globals; no allocation allowed)
__device__ float g_s[BB * FI];                 // per-channel modulation
__device__ float g_d[BB * FO];                 // demod factors
__device__ float g_wt[FI * KK * KK * FO];      // transposed, pre-scaled weights: [(fi*9+kk)][fo]

// ---------------------------------------------------------------------------
// Kernel 1: s[b,i] = fc_b[i] + fc_scale * sum_j style[b,j] * fc_w[i,j]
// ---------------------------------------------------------------------------
__global__ void k_style(const float* __restrict__ style,
                        const float* __restrict__ fc_w,
                        const float* __restrict__ fc_b) {
    int b = blockIdx.x;
    __shared__ float st[DSTYLE];
    for (int j = threadIdx.x; j < DSTYLE; j += blockDim.x)
        st[j] = style[b * DSTYLE + j];
    __syncthreads();
    for (int i = threadIdx.x; i < FI; i += blockDim.x) {
        const float* wr = fc_w + (size_t)i * DSTYLE;
        float acc = 0.f;
        #pragma unroll 8
        for (int j = 0; j < DSTYLE; ++j) acc += st[j] * wr[j];
        g_s[b * FI + i] = acc * FC_SCALE + fc_b[i];
    }
}

// ---------------------------------------------------------------------------
// Kernel 2: transpose + pre-scale weights: g_wt[t*FO + fo] = w[fo*4608 + t]*ws
// ---------------------------------------------------------------------------
__global__ void k_wt(const float* __restrict__ w) {
    int idx = blockIdx.x * blockDim.x + threadIdx.x;
    if (idx >= FI * KK * KK * FO) return;
    int fo = idx & (FO - 1);
    int t  = idx >> 9;                           // fi*9 + kk, 0..4607
    g_wt[(size_t)t * FO + fo] = w[(size_t)fo * (FI * KK * KK) + t] * W_SCALE;
}

// ---------------------------------------------------------------------------
// Kernel 3: d[b,fo] = rsqrt( ws^2 * sum_fi (sum_k w^2) * s[b,fi]^2 + eps )
// ---------------------------------------------------------------------------
__global__ void k_demod(const float* __restrict__ w) {
    int fo = blockIdx.x;
    float p[BB];
    #pragma unroll
    for (int b = 0; b < BB; ++b) p[b] = 0.f;

    for (int fi = threadIdx.x; fi < FI; fi += blockDim.x) {
        const float* wp = w + ((size_t)fo * FI + fi) * (KK * KK);
        float wsq = 0.f;
        #pragma unroll
        for (int k = 0; k < KK * KK; ++k) { float v = wp[k]; wsq += v * v; }
        #pragma unroll
        for (int b = 0; b < BB; ++b) {
            float sv = g_s[b * FI + fi];
            p[b] += wsq * sv * sv;
        }
    }
    __shared__ float red[BB][256];
    #pragma unroll
    for (int b = 0; b < BB; ++b) red[b][threadIdx.x] = p[b];
    __syncthreads();
    for (int off = 128; off > 0; off >>= 1) {
        if (threadIdx.x < off) {
            #pragma unroll
            for (int b = 0; b < BB; ++b)
                red[b][threadIdx.x] += red[b][threadIdx.x + off];
        }
        __syncthreads();
    }
    if (threadIdx.x < BB) {
        float sum = red[threadIdx.x][0] * (W_SCALE * W_SCALE) + EPSI;
        g_d[threadIdx.x * FO + fo] = rsqrtf(sum);
    }
}

// ---------------------------------------------------------------------------
// Kernel 4: main conv.  Block: 64 fo x (2 rows x 64 cols), one b.
// Thread (16x16): 4 fo x (2 rows x 4 cols) register tile = 32 accumulators.
// s folded into smem x-tile fill; d folded into epilogue.
// ---------------------------------------------------------------------------
__global__ void __launch_bounds__(256, 3)
k_conv(const float* __restrict__ x, float* __restrict__ y) {
    extern __shared__ float smem[];
    float* sw = smem;                         // [FI_CHUNK*9][FO_TILE] = 9216 floats
    float* sx = smem + FI_CHUNK * 9 * FO_TILE; // [FI_CHUNK][4][SXW]   = 4352 floats

    const int tid = threadIdx.x;
    const int tx  = tid & 15;      // pixel-column group: cols tx*4 .. tx*4+3
    const int ty  = tid >> 4;      // fo group: fo ty*4 .. ty*4+3

    const int rb0 = blockIdx.x * TH;            // output row base
    const int foB = blockIdx.y * FO_TILE;       // fo tile base
    const int b   = blockIdx.z;

    const float* xg = x + (size_t)b * FI * HH * WW;

    float acc[TH][4][4];
    #pragma unroll
    for (int r = 0; r < TH; ++r)
        #pragma unroll
        for (int c = 0; c < 4; ++c)
            #pragma unroll
            for (int j = 0; j < 4; ++j) acc[r][c][j] = 0.f;

    for (int fic = 0; fic < FI; fic += FI_CHUNK) {
        // --- load weight chunk (coalesced from g_wt), float4 ---
        {
            const int n4 = FI_CHUNK * 9 * FO_TILE / 4;   // 2304
            #pragma unroll
            for (int it = 0; it < n4 / 256; ++it) {
                int i   = it * 256 + tid;
                int row = i >> 4;        // 0..143 = fi_local*9+kk
                int c4  = i & 15;
                float4 v = *(const float4*)&g_wt[(size_t)(fic * 9 + row) * FO + foB + c4 * 4];
                *(float4*)&sw[row * FO_TILE + c4 * 4] = v;
            }
        }
        // --- load x chunk with halo, fold s ---
        {
            const int n = FI_CHUNK * 4 * 66;             // 4224
            for (int i = tid; i < n; i += 256) {
                int fi  = i / 264;
                int rem = i - fi * 264;
                int ir  = rem / 66;
                int ic  = rem - ir * 66;
                int gr  = rb0 + ir - 1;
                int gc  = ic - 1;
                float v = 0.f;
                if (gr >= 0 && gr < HH && gc >= 0 && gc < WW)
                    v = xg[((size_t)(fic + fi) * HH + gr) * WW + gc] * g_s[b * FI + fic + fi];
                sx[fi * SX_PLANE + ir * SXW + ic] = v;
            }
        }
        __syncthreads();

        #pragma unroll 1
        for (int fi = 0; fi < FI_CHUNK; ++fi) {
            // x rows 0..3, cols tx*4 .. tx*4+5 (6 values; reused across kw)
            float xv[4][6];
            const float* xb = &sx[fi * SX_PLANE + tx * 4];
            #pragma unroll
            for (int ir = 0; ir < 4; ++ir) {
                float4 a = *(const float4*)&xb[ir * SXW];
                float2 e = *(const float2*)&xb[ir * SXW + 4];
                xv[ir][0] = a.x; xv[ir][1] = a.y; xv[ir][2] = a.z;
                xv[ir][3] = a.w; xv[ir][4] = e.x; xv[ir][5] = e.y;
            }
            const float* wb = &sw[fi * 9 * FO_TILE + ty * 4];
            #pragma unroll
            for (int kh = 0; kh < 3; ++kh) {
                #pragma unroll
                for (int kw = 0; kw < 3; ++kw) {
                    float4 wv = *(const float4*)&wb[(kh * 3 + kw) * FO_TILE];
                    #pragma unroll
                    for (int r = 0; r < TH; ++r) {
                        #pragma unroll
                        for (int c = 0; c < 4; ++c) {
                            float xs = xv[r + kh][c + kw];
                            acc[r][c][0] += xs * wv.x;
                            acc[r][c][1] += xs * wv.y;
                            acc[r][c][2] += xs * wv.z;
                            acc[r][c][3] += xs * wv.w;
                        }
                    }
                }
            }
        }
        __syncthreads();
    }

    // --- epilogue: apply demod, store float4 ---
    float dv[4];
    #pragma unroll
    for (int j = 0; j < 4; ++j)
        dv[j] = g_d[b * FO + foB + ty * 4 + j];

    #pragma unroll
    for (int r = 0; r < TH; ++r) {
        #pragma unroll
        for (int j = 0; j < 4; ++j) {
            float4 o;
            o.x = acc[r][0][j] * dv[j];
            o.y = acc[r][1][j] * dv[j];
            o.z = acc[r][2][j] * dv[j];
            o.w = acc[r][3][j] * dv[j];
            size_t oi = (((size_t)b * FO + foB + ty * 4 + j) * HH + rb0 + r) * WW + tx * 4;
            *(float4*)&y[oi] = o;
        }
    }
}

// ---------------------------------------------------------------------------
extern "C" void kernel_launch(void* const* d_in, const int* in_sizes, int n_in,
                              void* d_out, int out_size) {
    const float* x     = (const float*)d_in[0];
    const float* style = (const float*)d_in[1];
    const float* w     = (const float*)d_in[2];
    const float* fc_w  = (const float*)d_in[3];
    const float* fc_b  = (const float*)d_in[4];
    float* y = (float*)d_out;

    static bool attr_set = false;
    const int conv_smem = (FI_CHUNK * 9 * FO_TILE + FI_CHUNK * SX_PLANE) * (int)sizeof(float); // 54272
    if (!attr_set) {
        cudaFuncSetAttribute(k_conv, cudaFuncAttributeMaxDynamicSharedMemorySize, conv_smem);
        attr_set = true;
    }

    k_style<<<BB, 256>>>(style, fc_w, fc_b);
    {
        int total = FI * KK * KK * FO;
        k_wt<<<(total + 255) / 256, 256>>>(w);
    }
    k_demod<<<FO, 256>>>(w);

    dim3 grid(HH / TH, FO / FO_TILE, BB);   // (32, 8, 8)
    k_conv<<<grid, 256, conv_smem>>>(x, y);
}

// round 5
// speedup vs baseline: 2.2188x; 2.2188x over previous
#include <cuda_runtime.h>
#include <cuda_fp16.h>
#include <cstdint>

// Problem constants
#define BB   8
#define FI   512
#define FO   512
#define HH   64
#define WW   64
#define DSTYLE 512
#define KTOT 4608                // 9 * 512

#define FC_SCALE 0.04419417382415922f      // 512^-0.5
#define W_SCALE  0.014731391274719739f     // (512*9)^-0.5
#define EPSI     1e-8f

// GEMM pipeline config
#define NSTG        3
#define STAGE_BYTES 32768        // A: 128x128B (16KB) + B: 128x128B (16KB)
#define SMEM_TOTAL  (NSTG*STAGE_BYTES)   // 98304
#define NCHUNK      144          // 9 kk * 16 fi-chunks of 32

// Scratch (device globals; no allocation allowed)
__device__ float  g_s[BB*FI];
__device__ float  g_d[BB*FO];
__device__ __half g_wh[(size_t)FO*KTOT];     // w_hi  [fo][kk*512+fi]
__device__ __half g_wl[(size_t)FO*KTOT];     // w_lo
__device__ __half g_xh[(size_t)BB*HH*WW*FI]; // xm_hi [b][r][c][fi]
__device__ __half g_xl[(size_t)BB*HH*WW*FI]; // xm_lo

// ---------------------------------------------------------------------------
// helpers
// ---------------------------------------------------------------------------
__device__ __forceinline__ uint32_t smem_u32(const void* p){
    uint32_t a;
    asm("{ .reg .u64 t; cvta.to.shared.u64 t, %1; cvt.u32.u64 %0, t; }"
        : "=r"(a) : "l"(p));
    return a;
}
__device__ __forceinline__ void cp16(uint32_t dst, const void* src, int srcsz){
    asm volatile("cp.async.cg.shared.global [%0], [%1], 16, %2;"
                 :: "r"(dst), "l"(src), "r"(srcsz) : "memory");
}
#define CP_COMMIT() asm volatile("cp.async.commit_group;" ::: "memory")
#define CP_WAIT1()  asm volatile("cp.async.wait_group 1;" ::: "memory")

#define LDSM4(r, addr) \
    asm volatile("ldmatrix.sync.aligned.m8n8.x4.shared.b16 {%0,%1,%2,%3}, [%4];" \
        : "=r"((r)[0]),"=r"((r)[1]),"=r"((r)[2]),"=r"((r)[3]) : "r"(addr))

__device__ __forceinline__ void mma16816(float* c, const uint32_t* a,
                                         uint32_t b0, uint32_t b1){
    asm volatile("mma.sync.aligned.m16n8k16.row.col.f32.f16.f16.f32 "
        "{%0,%1,%2,%3}, {%4,%5,%6,%7}, {%8,%9}, {%0,%1,%2,%3};"
        : "+f"(c[0]),"+f"(c[1]),"+f"(c[2]),"+f"(c[3])
        : "r"(a[0]),"r"(a[1]),"r"(a[2]),"r"(a[3]), "r"(b0),"r"(b1));
}

// ---------------------------------------------------------------------------
// Kernel 1: s[b,i] = fc_b[i] + fc_scale * sum_j style[b,j] * fc_w[i,j]
// ---------------------------------------------------------------------------
__global__ void k_style(const float* __restrict__ style,
                        const float* __restrict__ fc_w,
                        const float* __restrict__ fc_b) {
    int b = blockIdx.x;
    __shared__ float st[DSTYLE];
    for (int j = threadIdx.x; j < DSTYLE; j += blockDim.x)
        st[j] = style[b * DSTYLE + j];
    __syncthreads();
    for (int i = threadIdx.x; i < FI; i += blockDim.x) {
        const float* wr = fc_w + (size_t)i * DSTYLE;
        float acc = 0.f;
        #pragma unroll 8
        for (int j = 0; j < DSTYLE; ++j) acc += st[j] * wr[j];
        g_s[b * FI + i] = acc * FC_SCALE + fc_b[i];
    }
}

// ---------------------------------------------------------------------------
// Kernel 2: fp16 hi/lo split of scaled weights, reordered to [fo][kk*512+fi]
// ---------------------------------------------------------------------------
__global__ void k_wsplit(const float* __restrict__ w) {
    int idx = blockIdx.x * blockDim.x + threadIdx.x;
    if (idx >= FO * KTOT) return;
    int fo  = idx / KTOT;
    int rem = idx - fo * KTOT;
    int kk  = rem >> 9;
    int fi  = rem & 511;
    float v = w[((size_t)(fo * FI + fi)) * 9 + kk] * W_SCALE;
    __half h = __float2half(v);
    __half l = __float2half(v - __half2float(h));
    g_wh[idx] = h;
    g_wl[idx] = l;
}

// ---------------------------------------------------------------------------
// Kernel 3: d[b,fo] = rsqrt( ws^2 * sum_fi (sum_k w^2) * s[b,fi]^2 + eps )
// ---------------------------------------------------------------------------
__global__ void k_demod(const float* __restrict__ w) {
    int fo = blockIdx.x;
    float p[BB];
    #pragma unroll
    for (int b = 0; b < BB; ++b) p[b] = 0.f;
    for (int fi = threadIdx.x; fi < FI; fi += blockDim.x) {
        const float* wp = w + ((size_t)fo * FI + fi) * 9;
        float wsq = 0.f;
        #pragma unroll
        for (int k = 0; k < 9; ++k) { float v = wp[k]; wsq += v * v; }
        #pragma unroll
        for (int b = 0; b < BB; ++b) {
            float sv = g_s[b * FI + fi];
            p[b] += wsq * sv * sv;
        }
    }
    __shared__ float red[BB][256];
    #pragma unroll
    for (int b = 0; b < BB; ++b) red[b][threadIdx.x] = p[b];
    __syncthreads();
    for (int off = 128; off > 0; off >>= 1) {
        if (threadIdx.x < off) {
            #pragma unroll
            for (int b = 0; b < BB; ++b)
                red[b][threadIdx.x] += red[b][threadIdx.x + off];
        }
        __syncthreads();
    }
    if (threadIdx.x < BB) {
        float sum = red[threadIdx.x][0] * (W_SCALE * W_SCALE) + EPSI;
        g_d[threadIdx.x * FO + fo] = rsqrtf(sum);
    }
}

// ---------------------------------------------------------------------------
// Kernel 4: xm = x*s, transposed to [b][r][c][fi], fp16 hi/lo split
// ---------------------------------------------------------------------------
__global__ void k_xsplit(const float* __restrict__ x) {
    int b   = blockIdx.z;
    int r   = blockIdx.y;
    int fic = blockIdx.x * 64;
    __shared__ float tile[64][65];
    __shared__ float sv[64];
    int t = threadIdx.x;
    if (t < 64) sv[t] = g_s[b * FI + fic + t];
    #pragma unroll
    for (int i = 0; i < 16; ++i) {
        int idx = i * 256 + t;
        int fi = idx >> 6, c = idx & 63;
        tile[fi][c] = x[(((size_t)(b * FI + fic + fi)) * HH + r) * WW + c];
    }
    __syncthreads();
    #pragma unroll
    for (int i = 0; i < 16; ++i) {
        int idx = i * 256 + t;
        int c = idx >> 6, fi = idx & 63;
        float v = tile[fi][c] * sv[fi];
        __half h = __float2half(v);
        __half l = __float2half(v - __half2float(h));
        size_t off = ((size_t)((b * HH + r) * WW + c) << 9) + fic + fi;
        g_xh[off] = h;
        g_xl[off] = l;
    }
}

// ---------------------------------------------------------------------------
// Stage loader via cp.async: A[128 px][128B = hi64|lo64], B[128 fo][128B]
// ---------------------------------------------------------------------------
__device__ __forceinline__ void load_stage(int s, int b, int r0, int foB,
                                           uint32_t smA, int tid) {
    int kk = s >> 4;
    int fc = (s & 15) << 5;                 // fi chunk base (32 halves)
    int kd = kk / 3;
    int dr = kd - 1, dc = kk - kd * 3 - 1;
    uint32_t smB = smA + 16384;
    // A: 1024 transfers of 16B
    #pragma unroll
    for (int p = 0; p < 4; ++p) {
        int slot = p * 256 + tid;
        int row = slot >> 3, j = slot & 7;
        int part = j >> 2, jj = j & 3;
        int rr = r0 + (row >> 6) + dr;
        int cc = (row & 63) + dc;
        const __half* src = part ? g_xl : g_xh;
        int ok  = ((unsigned)rr < (unsigned)HH) & ((unsigned)cc < (unsigned)WW);
        int off = ok ? ((((b * HH + rr) * WW + cc) << 9) + fc + jj * 8) : 0;
        uint32_t dst = smA + row * 128 + ((part * 64 + jj * 16) ^ ((row & 7) << 4));
        cp16(dst, src + off, ok ? 16 : 0);
    }
    // B: 1024 transfers of 16B
    #pragma unroll
    for (int p = 0; p < 4; ++p) {
        int slot = p * 256 + tid;
        int fo = slot >> 3, j = slot & 7;
        int part = j >> 2, jj = j & 3;
        const __half* src = part ? g_wl : g_wh;
        int off = (foB + fo) * KTOT + (kk << 9) + fc + jj * 8;
        uint32_t dst = smB + fo * 128 + ((part * 64 + jj * 16) ^ ((fo & 7) << 4));
        cp16(dst, src + off, 16);
    }
}

// ---------------------------------------------------------------------------
// Kernel 5: implicit-GEMM conv on mma.sync (fp16 split, fp32 accum)
// CTA: M=128 px (2 rows x 64 cols), N=128 fo. 8 warps, warp tile 64x32.
// ---------------------------------------------------------------------------
__global__ void __launch_bounds__(256)
k_conv_mma(float* __restrict__ y) {
    extern __shared__ char smem[];
    uint32_t sb = smem_u32(smem);
    const int tid = threadIdx.x;
    const int r0  = blockIdx.x * 2;
    const int foB = blockIdx.y * 128;
    const int b   = blockIdx.z;
    const int w   = tid >> 5, l = tid & 31;
    const int wm  = w >> 2, wn = w & 3;

    float acc[4][4][4];
    #pragma unroll
    for (int i = 0; i < 4; ++i)
        #pragma unroll
        for (int j = 0; j < 4; ++j)
            #pragma unroll
            for (int k = 0; k < 4; ++k) acc[i][j][k] = 0.f;

    // prologue: stages 0,1
    load_stage(0, b, r0, foB, sb, tid);               CP_COMMIT();
    load_stage(1, b, r0, foB, sb + STAGE_BYTES, tid); CP_COMMIT();

    // ldmatrix address components (swizzle: chunk ^= (row&7)<<4 within 128B row)
    uint32_t aoff[4], ax7[4];
    #pragma unroll
    for (int am = 0; am < 4; ++am) {
        int rowA = wm * 64 + am * 16 + (l & 15);
        aoff[am] = (uint32_t)rowA * 128;
        ax7[am]  = (uint32_t)(rowA & 7) << 4;
    }
    const uint32_t acol = ((l >> 4) & 1) * 16;
    uint32_t boff[2], bx7[2];
    #pragma unroll
    for (int bp = 0; bp < 2; ++bp) {
        int rowB = wn * 32 + bp * 16 + ((l >> 4) << 3) + (l & 7);
        boff[bp] = 16384u + (uint32_t)rowB * 128;
        bx7[bp]  = (uint32_t)(rowB & 7) << 4;
    }
    const uint32_t bcol = ((l >> 3) & 1) * 16;

    for (int s = 0; s < NCHUNK; ++s) {
        CP_WAIT1();
        __syncthreads();
        if (s + 2 < NCHUNK)
            load_stage(s + 2, b, r0, foB,
                       sb + (uint32_t)((s + 2) % NSTG) * STAGE_BYTES, tid);
        CP_COMMIT();

        uint32_t st = sb + (uint32_t)(s % NSTG) * STAGE_BYTES;
        #pragma unroll
        for (int kst = 0; kst < 2; ++kst) {
            const uint32_t kb = (uint32_t)kst * 32;
            uint32_t ah[4][4], al[4][4], bh[2][4], bl[2][4];
            // A hi, B hi
            #pragma unroll
            for (int am = 0; am < 4; ++am)
                LDSM4(ah[am], st + aoff[am] + ((acol + kb) ^ ax7[am]));
            #pragma unroll
            for (int bp = 0; bp < 2; ++bp)
                LDSM4(bh[bp], st + boff[bp] + ((bcol + kb) ^ bx7[bp]));
            // hh
            #pragma unroll
            for (int am = 0; am < 4; ++am)
                #pragma unroll
                for (int bn = 0; bn < 4; ++bn) {
                    int bp = bn >> 1, h = (bn & 1) * 2;
                    mma16816(acc[am][bn], ah[am], bh[bp][h], bh[bp][h + 1]);
                }
            // B lo; hl = Ah*Bl
            #pragma unroll
            for (int bp = 0; bp < 2; ++bp)
                LDSM4(bl[bp], st + boff[bp] + ((bcol + kb + 64) ^ bx7[bp]));
            #pragma unroll
            for (int am = 0; am < 4; ++am)
                #pragma unroll
                for (int bn = 0; bn < 4; ++bn) {
                    int bp = bn >> 1, h = (bn & 1) * 2;
                    mma16816(acc[am][bn], ah[am], bl[bp][h], bl[bp][h + 1]);
                }
            // A lo; lh = Al*Bh
            #pragma unroll
            for (int am = 0; am < 4; ++am)
                LDSM4(al[am], st + aoff[am] + ((acol + kb + 64) ^ ax7[am]));
            #pragma unroll
            for (int am = 0; am < 4; ++am)
                #pragma unroll
                for (int bn = 0; bn < 4; ++bn) {
                    int bp = bn >> 1, h = (bn & 1) * 2;
                    mma16816(acc[am][bn], al[am], bh[bp][h], bh[bp][h + 1]);
                }
        }
    }

    // epilogue: apply demod, scatter to NCHW
    const float* dp = g_d + b * FO + foB;
    const int mlow = l >> 2;
    #pragma unroll
    for (int am = 0; am < 4; ++am) {
        int m0 = wm * 64 + am * 16 + mlow;
        int rr0 = r0 + (m0 >> 6), cc0 = m0 & 63;
        int m1 = m0 + 8;
        int rr1 = r0 + (m1 >> 6), cc1 = m1 & 63;
        #pragma unroll
        for (int bn = 0; bn < 4; ++bn) {
            int n = wn * 32 + bn * 8 + (l & 3) * 2;
            float d0 = dp[n], d1 = dp[n + 1];
            size_t base0 = ((size_t)((b * FO + foB + n)     * HH)) * WW;
            size_t base1 = ((size_t)((b * FO + foB + n + 1) * HH)) * WW;
            y[base0 + (size_t)rr0 * WW + cc0] = acc[am][bn][0] * d0;
            y[base1 + (size_t)rr0 * WW + cc0] = acc[am][bn][1] * d1;
            y[base0 + (size_t)rr1 * WW + cc1] = acc[am][bn][2] * d0;
            y[base1 + (size_t)rr1 * WW + cc1] = acc[am][bn][3] * d1;
        }
    }
}

// ---------------------------------------------------------------------------
extern "C" void kernel_launch(void* const* d_in, const int* in_sizes, int n_in,
                              void* d_out, int out_size) {
    const float* x     = (const float*)d_in[0];
    const float* style = (const float*)d_in[1];
    const float* w     = (const float*)d_in[2];
    const float* fc_w  = (const float*)d_in[3];
    const float* fc_b  = (const float*)d_in[4];
    float* y = (float*)d_out;

    static bool attr_set = false;
    if (!attr_set) {
        cudaFuncSetAttribute(k_conv_mma, cudaFuncAttributeMaxDynamicSharedMemorySize, SMEM_TOTAL);
        attr_set = true;
    }

    k_style<<<BB, 256>>>(style, fc_w, fc_b);
    k_wsplit<<<(FO * KTOT + 255) / 256, 256>>>(w);
    k_demod<<<FO, 256>>>(w);
    {
        dim3 g(FI / 64, HH, BB);   // (8, 64, 8)
        k_xsplit<<<g, 256>>>(x);
    }
    {
        dim3 g(HH / 2, FO / 128, BB);   // (32, 4, 8)
        k_conv_mma<<<g, 256, SMEM_TOTAL>>>(y);
    }
}

// round 10
// speedup vs baseline: 3.4135x; 1.5384x over previous
#include <cuda_runtime.h>
#include <cuda_fp16.h>
#include <cstdint>

// Problem constants
#define BB   8
#define FI   512
#define FO   512
#define HH   64
#define WW   64
#define DSTYLE 512
#define KTOT 4608                // 9 * 512

#define FC_SCALE 0.04419417382415922f      // 512^-0.5
#define W_SCALE  0.014731391274719739f     // (512*9)^-0.5
#define EPSI     1e-8f

// GEMM pipeline config
#define NSTG        4
#define A_BYTES     16384        // 128 rows x 128B (hi64|lo64)
#define B_ROWB      80           // 64B data + 16B pad (conflict-free, no swizzle)
#define B_BYTES     (128*B_ROWB) // 10240
#define STAGE_BYTES (A_BYTES + B_BYTES)        // 26624
#define SMEM_TOTAL  (NSTG*STAGE_BYTES)         // 106496
#define NCHUNK      144          // 9 kk * 16 fi-chunks of 32

// Scratch (device globals; no allocation allowed)
__device__ float  g_s[BB*FI];
__device__ float  g_d[BB*FO];
__device__ __half g_wh[(size_t)FO*KTOT];     // w_hi  [fo][kk*512+fi]
__device__ __half g_xh[(size_t)BB*HH*WW*FI]; // xm_hi [b][r][c][fi]
__device__ __half g_xl[(size_t)BB*HH*WW*FI]; // xm_lo

// ---------------------------------------------------------------------------
// helpers
// ---------------------------------------------------------------------------
__device__ __forceinline__ uint32_t smem_u32(const void* p){
    uint32_t a;
    asm("{ .reg .u64 t; cvta.to.shared.u64 t, %1; cvt.u32.u64 %0, t; }"
        : "=r"(a) : "l"(p));
    return a;
}
__device__ __forceinline__ void cp16(uint32_t dst, const void* src, int srcsz){
    asm volatile("cp.async.cg.shared.global [%0], [%1], 16, %2;"
                 :: "r"(dst), "l"(src), "r"(srcsz) : "memory");
}
#define CP_COMMIT() asm volatile("cp.async.commit_group;" ::: "memory")
#define CP_WAIT2()  asm volatile("cp.async.wait_group 2;" ::: "memory")

#define LDSM4(r, addr) \
    asm volatile("ldmatrix.sync.aligned.m8n8.x4.shared.b16 {%0,%1,%2,%3}, [%4];" \
        : "=r"((r)[0]),"=r"((r)[1]),"=r"((r)[2]),"=r"((r)[3]) : "r"(addr))

__device__ __forceinline__ void mma16816(float* c, const uint32_t* a,
                                         uint32_t b0, uint32_t b1){
    asm volatile("mma.sync.aligned.m16n8k16.row.col.f32.f16.f16.f32 "
        "{%0,%1,%2,%3}, {%4,%5,%6,%7}, {%8,%9}, {%0,%1,%2,%3};"
        : "+f"(c[0]),"+f"(c[1]),"+f"(c[2]),"+f"(c[3])
        : "r"(a[0]),"r"(a[1]),"r"(a[2]),"r"(a[3]), "r"(b0),"r"(b1));
}

// ---------------------------------------------------------------------------
// Kernel 1: s[b,i] = fc_b[i] + fc_scale * sum_j style[b,j] * fc_w[i,j]
// ---------------------------------------------------------------------------
__global__ void k_style(const float* __restrict__ style,
                        const float* __restrict__ fc_w,
                        const float* __restrict__ fc_b) {
    int b = blockIdx.x;
    __shared__ float st[DSTYLE];
    for (int j = threadIdx.x; j < DSTYLE; j += blockDim.x)
        st[j] = style[b * DSTYLE + j];
    __syncthreads();
    for (int i = threadIdx.x; i < FI; i += blockDim.x) {
        const float* wr = fc_w + (size_t)i * DSTYLE;
        float acc = 0.f;
        #pragma unroll 8
        for (int j = 0; j < DSTYLE; ++j) acc += st[j] * wr[j];
        g_s[b * FI + i] = acc * FC_SCALE + fc_b[i];
    }
}

// ---------------------------------------------------------------------------
// Kernel 2: fp16 (hi only) of scaled weights, reordered to [fo][kk*512+fi]
// ---------------------------------------------------------------------------
__global__ void k_wsplit(const float* __restrict__ w) {
    int idx = blockIdx.x * blockDim.x + threadIdx.x;
    if (idx >= FO * KTOT) return;
    int fo  = idx / KTOT;
    int rem = idx - fo * KTOT;
    int kk  = rem >> 9;
    int fi  = rem & 511;
    float v = w[((size_t)(fo * FI + fi)) * 9 + kk] * W_SCALE;
    g_wh[idx] = __float2half(v);
}

// ---------------------------------------------------------------------------
// Kernel 3: d[b,fo] = rsqrt( ws^2 * sum_fi (sum_k w^2) * s[b,fi]^2 + eps )
// ---------------------------------------------------------------------------
__global__ void k_demod(const float* __restrict__ w) {
    int fo = blockIdx.x;
    float p[BB];
    #pragma unroll
    for (int b = 0; b < BB; ++b) p[b] = 0.f;
    for (int fi = threadIdx.x; fi < FI; fi += blockDim.x) {
        const float* wp = w + ((size_t)fo * FI + fi) * 9;
        float wsq = 0.f;
        #pragma unroll
        for (int k = 0; k < 9; ++k) { float v = wp[k]; wsq += v * v; }
        #pragma unroll
        for (int b = 0; b < BB; ++b) {
            float sv = g_s[b * FI + fi];
            p[b] += wsq * sv * sv;
        }
    }
    __shared__ float red[BB][256];
    #pragma unroll
    for (int b = 0; b < BB; ++b) red[b][threadIdx.x] = p[b];
    __syncthreads();
    for (int off = 128; off > 0; off >>= 1) {
        if (threadIdx.x < off) {
            #pragma unroll
            for (int b = 0; b < BB; ++b)
                red[b][threadIdx.x] += red[b][threadIdx.x + off];
        }
        __syncthreads();
    }
    if (threadIdx.x < BB) {
        float sum = red[threadIdx.x][0] * (W_SCALE * W_SCALE) + EPSI;
        g_d[threadIdx.x * FO + fo] = rsqrtf(sum);
    }
}

// ---------------------------------------------------------------------------
// Kernel 4: xm = x*s, transposed to [b][r][c][fi], fp16 hi/lo split
// ---------------------------------------------------------------------------
__global__ void k_xsplit(const float* __restrict__ x) {
    int b   = blockIdx.z;
    int r   = blockIdx.y;
    int fic = blockIdx.x * 64;
    __shared__ float tile[64][65];
    __shared__ float sv[64];
    int t = threadIdx.x;
    if (t < 64) sv[t] = g_s[b * FI + fic + t];
    #pragma unroll
    for (int i = 0; i < 16; ++i) {
        int idx = i * 256 + t;
        int fi = idx >> 6, c = idx & 63;
        tile[fi][c] = x[(((size_t)(b * FI + fic + fi)) * HH + r) * WW + c];
    }
    __syncthreads();
    #pragma unroll
    for (int i = 0; i < 16; ++i) {
        int idx = i * 256 + t;
        int c = idx >> 6, fi = idx & 63;
        float v = tile[fi][c] * sv[fi];
        __half h = __float2half(v);
        __half l = __float2half(v - __half2float(h));
        size_t off = ((size_t)((b * HH + r) * WW + c) << 9) + fic + fi;
        g_xh[off] = h;
        g_xl[off] = l;
    }
}

// ---------------------------------------------------------------------------
// Stage loader via cp.async:
//   A[128 px][128B = hi64|lo64] swizzled;  B[128 fo][80B rows, 64B data]
// ---------------------------------------------------------------------------
__device__ __forceinline__ void load_stage(int s, int b, int r0, int foB,
                                           uint32_t smA, int tid) {
    int kk = s >> 4;
    int fc = (s & 15) << 5;                 // fi chunk base (32 halves)
    int kd = kk / 3;
    int dr = kd - 1, dc = kk - kd * 3 - 1;
    uint32_t smB = smA + A_BYTES;
    // A: 1024 transfers of 16B
    #pragma unroll
    for (int p = 0; p < 4; ++p) {
        int slot = p * 256 + tid;
        int row = slot >> 3, j = slot & 7;
        int part = j >> 2, jj = j & 3;
        int rr = r0 + (row >> 6) + dr;
        int cc = (row & 63) + dc;
        const __half* src = part ? g_xl : g_xh;
        int ok  = ((unsigned)rr < (unsigned)HH) & ((unsigned)cc < (unsigned)WW);
        int off = ok ? ((((b * HH + rr) * WW + cc) << 9) + fc + jj * 8) : 0;
        uint32_t dst = smA + row * 128 + ((part * 64 + jj * 16) ^ ((row & 7) << 4));
        cp16(dst, src + off, ok ? 16 : 0);
    }
    // B (hi only): 512 transfers of 16B
    #pragma unroll
    for (int p = 0; p < 2; ++p) {
        int slot = p * 256 + tid;
        int fo = slot >> 2, jj = slot & 3;
        int off = (foB + fo) * KTOT + (kk << 9) + fc + jj * 8;
        uint32_t dst = smB + fo * B_ROWB + jj * 16;
        cp16(dst, g_wh + off, 16);
    }
}

// ---------------------------------------------------------------------------
// Kernel 5: implicit-GEMM conv on mma.sync (2-term: (Ah+Al)*Bh, fp32 accum)
// CTA: M=128 px (2 rows x 64 cols), N=128 fo. 8 warps, warp tile 64x32.
// ---------------------------------------------------------------------------
__global__ void __launch_bounds__(256, 2)
k_conv_mma(float* __restrict__ y) {
    extern __shared__ char smem[];
    uint32_t sb = smem_u32(smem);
    const int tid = threadIdx.x;
    const int r0  = blockIdx.x * 2;
    const int foB = blockIdx.y * 128;
    const int b   = blockIdx.z;
    const int w   = tid >> 5, l = tid & 31;
    const int wm  = w >> 2, wn = w & 3;

    float acc[4][4][4];
    #pragma unroll
    for (int i = 0; i < 4; ++i)
        #pragma unroll
        for (int j = 0; j < 4; ++j)
            #pragma unroll
            for (int k = 0; k < 4; ++k) acc[i][j][k] = 0.f;

    // prologue: stages 0,1,2
    load_stage(0, b, r0, foB, sb, tid);                   CP_COMMIT();
    load_stage(1, b, r0, foB, sb + STAGE_BYTES, tid);     CP_COMMIT();
    load_stage(2, b, r0, foB, sb + 2 * STAGE_BYTES, tid); CP_COMMIT();

    // ldmatrix address components
    uint32_t aoff[4], ax7[4];
    #pragma unroll
    for (int am = 0; am < 4; ++am) {
        int rowA = wm * 64 + am * 16 + (l & 15);
        aoff[am] = (uint32_t)rowA * 128;
        ax7[am]  = (uint32_t)(rowA & 7) << 4;
    }
    const uint32_t acol = ((l >> 4) & 1) * 16;
    uint32_t boff[2];
    #pragma unroll
    for (int bp = 0; bp < 2; ++bp) {
        int rowB = wn * 32 + bp * 16 + ((l >> 4) << 3) + (l & 7);
        boff[bp] = (uint32_t)A_BYTES + (uint32_t)rowB * B_ROWB;
    }
    const uint32_t bcol = ((l >> 3) & 1) * 16;

    for (int s = 0; s < NCHUNK; ++s) {
        CP_WAIT2();
        __syncthreads();
        if (s + 3 < NCHUNK)
            load_stage(s + 3, b, r0, foB,
                       sb + (uint32_t)((s + 3) % NSTG) * STAGE_BYTES, tid);
        CP_COMMIT();

        uint32_t st = sb + (uint32_t)(s % NSTG) * STAGE_BYTES;
        #pragma unroll
        for (int kst = 0; kst < 2; ++kst) {
            const uint32_t kb = (uint32_t)kst * 32;
            uint32_t ah[4][4], al[4][4], bh[2][4];
            #pragma unroll
            for (int bp = 0; bp < 2; ++bp)
                LDSM4(bh[bp], st + boff[bp] + bcol + kb);
            #pragma unroll
            for (int am = 0; am < 4; ++am)
                LDSM4(ah[am], st + aoff[am] + ((acol + kb) ^ ax7[am]));
            // hh
            #pragma unroll
            for (int am = 0; am < 4; ++am)
                #pragma unroll
                for (int bn = 0; bn < 4; ++bn) {
                    int bp = bn >> 1, h = (bn & 1) * 2;
                    mma16816(acc[am][bn], ah[am], bh[bp][h], bh[bp][h + 1]);
                }
            // A lo; lh = Al*Bh
            #pragma unroll
            for (int am = 0; am < 4; ++am)
                LDSM4(al[am], st + aoff[am] + ((acol + kb + 64) ^ ax7[am]));
            #pragma unroll
            for (int am = 0; am < 4; ++am)
                #pragma unroll
                for (int bn = 0; bn < 4; ++bn) {
                    int bp = bn >> 1, h = (bn & 1) * 2;
                    mma16816(acc[am][bn], al[am], bh[bp][h], bh[bp][h + 1]);
                }
        }
    }

    // epilogue: apply demod, scatter to NCHW
    const float* dp = g_d + b * FO + foB;
    const int mlow = l >> 2;
    #pragma unroll
    for (int am = 0; am < 4; ++am) {
        int m0 = wm * 64 + am * 16 + mlow;
        int rr0 = r0 + (m0 >> 6), cc0 = m0 & 63;
        int m1 = m0 + 8;
        int rr1 = r0 + (m1 >> 6), cc1 = m1 & 63;
        #pragma unroll
        for (int bn = 0; bn < 4; ++bn) {
            int n = wn * 32 + bn * 8 + (l & 3) * 2;
            float d0 = dp[n], d1 = dp[n + 1];
            size_t base0 = ((size_t)((b * FO + foB + n)     * HH)) * WW;
            size_t base1 = ((size_t)((b * FO + foB + n + 1) * HH)) * WW;
            y[base0 + (size_t)rr0 * WW + cc0] = acc[am][bn][0] * d0;
            y[base1 + (size_t)rr0 * WW + cc0] = acc[am][bn][1] * d1;
            y[base0 + (size_t)rr1 * WW + cc1] = acc[am][bn][2] * d0;
            y[base1 + (size_t)rr1 * WW + cc1] = acc[am][bn][3] * d1;
        }
    }
}

// ---------------------------------------------------------------------------
extern "C" void kernel_launch(void* const* d_in, const int* in_sizes, int n_in,
                              void* d_out, int out_size) {
    const float* x     = (const float*)d_in[0];
    const float* style = (const float*)d_in[1];
    const float* w     = (const float*)d_in[2];
    const float* fc_w  = (const float*)d_in[3];
    const float* fc_b  = (const float*)d_in[4];
    float* y = (float*)d_out;

    static bool attr_set = false;
    if (!attr_set) {
        cudaFuncSetAttribute(k_conv_mma, cudaFuncAttributeMaxDynamicSharedMemorySize, SMEM_TOTAL);
        attr_set = true;
    }

    k_style<<<BB, 256>>>(style, fc_w, fc_b);
    k_wsplit<<<(FO * KTOT + 255) / 256, 256>>>(w);
    k_demod<<<FO, 256>>>(w);
    {
        dim3 g(FI / 64, HH, BB);   // (8, 64, 8)
        k_xsplit<<<g, 256>>>(x);
    }
    {
        dim3 g(HH / 2, FO / 128, BB);   // (32, 4, 8)
        k_conv_mma<<<g, 256, SMEM_TOTAL>>>(y);
    }
}

// round 11
// speedup vs baseline: 5.0532x; 1.4803x over previous
#include <cuda_runtime.h>
#include <cuda_fp16.h>
#include <cstdint>

// Problem constants
#define BB   8
#define FI   512
#define FO   512
#define HH   64
#define WW   64
#define DSTYLE 512
#define KTOT 4608                // 9 * 512

#define FC_SCALE 0.04419417382415922f      // 512^-0.5
#define W_SCALE  0.014731391274719739f     // (512*9)^-0.5
#define EPSI     1e-8f

// GEMM pipeline config
#define NSTG        4
#define ROWB        80           // 64B data + 16B pad -> conflict-free ldmatrix, no swizzle
#define A_BYTES     (128*ROWB)   // 10240
#define B_BYTES     (128*ROWB)   // 10240
#define STAGE_BYTES (A_BYTES + B_BYTES)        // 20480
#define SMEM_TOTAL  (NSTG*STAGE_BYTES)         // 81920
#define NCHUNK      144          // 9 kk * 16 fi-chunks of 32

// Scratch (device globals; no allocation allowed)
__device__ float  g_s[BB*FI];
__device__ float  g_d[BB*FO];
__device__ __half g_wh[(size_t)FO*KTOT];     // w_hi  [fo][kk*512+fi]
__device__ __half g_xh[(size_t)BB*HH*WW*FI]; // xm_hi [b][r][c][fi]

// ---------------------------------------------------------------------------
// helpers
// ---------------------------------------------------------------------------
__device__ __forceinline__ uint32_t smem_u32(const void* p){
    uint32_t a;
    asm("{ .reg .u64 t; cvta.to.shared.u64 t, %1; cvt.u32.u64 %0, t; }"
        : "=r"(a) : "l"(p));
    return a;
}
__device__ __forceinline__ void cp16(uint32_t dst, const void* src, int srcsz){
    asm volatile("cp.async.cg.shared.global [%0], [%1], 16, %2;"
                 :: "r"(dst), "l"(src), "r"(srcsz) : "memory");
}
#define CP_COMMIT() asm volatile("cp.async.commit_group;" ::: "memory")
#define CP_WAIT2()  asm volatile("cp.async.wait_group 2;" ::: "memory")

#define LDSM4(r, addr) \
    asm volatile("ldmatrix.sync.aligned.m8n8.x4.shared.b16 {%0,%1,%2,%3}, [%4];" \
        : "=r"((r)[0]),"=r"((r)[1]),"=r"((r)[2]),"=r"((r)[3]) : "r"(addr))

__device__ __forceinline__ void mma16816(float* c, const uint32_t* a,
                                         uint32_t b0, uint32_t b1){
    asm volatile("mma.sync.aligned.m16n8k16.row.col.f32.f16.f16.f32 "
        "{%0,%1,%2,%3}, {%4,%5,%6,%7}, {%8,%9}, {%0,%1,%2,%3};"
        : "+f"(c[0]),"+f"(c[1]),"+f"(c[2]),"+f"(c[3])
        : "r"(a[0]),"r"(a[1]),"r"(a[2]),"r"(a[3]), "r"(b0),"r"(b1));
}

// ---------------------------------------------------------------------------
// Kernel 1: s[b,i] = fc_b[i] + fc_scale * sum_j style[b,j] * fc_w[i,j]
// ---------------------------------------------------------------------------
__global__ void k_style(const float* __restrict__ style,
                        const float* __restrict__ fc_w,
                        const float* __restrict__ fc_b) {
    int b = blockIdx.x;
    __shared__ float st[DSTYLE];
    for (int j = threadIdx.x; j < DSTYLE; j += blockDim.x)
        st[j] = style[b * DSTYLE + j];
    __syncthreads();
    for (int i = threadIdx.x; i < FI; i += blockDim.x) {
        const float* wr = fc_w + (size_t)i * DSTYLE;
        float acc = 0.f;
        #pragma unroll 8
        for (int j = 0; j < DSTYLE; ++j) acc += st[j] * wr[j];
        g_s[b * FI + i] = acc * FC_SCALE + fc_b[i];
    }
}

// ---------------------------------------------------------------------------
// Kernel 2: fp16 of scaled weights, reordered to [fo][kk*512+fi]
// ---------------------------------------------------------------------------
__global__ void k_wsplit(const float* __restrict__ w) {
    int idx = blockIdx.x * blockDim.x + threadIdx.x;
    if (idx >= FO * KTOT) return;
    int fo  = idx / KTOT;
    int rem = idx - fo * KTOT;
    int kk  = rem >> 9;
    int fi  = rem & 511;
    float v = w[((size_t)(fo * FI + fi)) * 9 + kk] * W_SCALE;
    g_wh[idx] = __float2half(v);
}

// ---------------------------------------------------------------------------
// Kernel 3: d[b,fo] = rsqrt( ws^2 * sum_fi (sum_k w^2) * s[b,fi]^2 + eps )
// ---------------------------------------------------------------------------
__global__ void k_demod(const float* __restrict__ w) {
    int fo = blockIdx.x;
    float p[BB];
    #pragma unroll
    for (int b = 0; b < BB; ++b) p[b] = 0.f;
    for (int fi = threadIdx.x; fi < FI; fi += blockDim.x) {
        const float* wp = w + ((size_t)fo * FI + fi) * 9;
        float wsq = 0.f;
        #pragma unroll
        for (int k = 0; k < 9; ++k) { float v = wp[k]; wsq += v * v; }
        #pragma unroll
        for (int b = 0; b < BB; ++b) {
            float sv = g_s[b * FI + fi];
            p[b] += wsq * sv * sv;
        }
    }
    __shared__ float red[BB][256];
    #pragma unroll
    for (int b = 0; b < BB; ++b) red[b][threadIdx.x] = p[b];
    __syncthreads();
    for (int off = 128; off > 0; off >>= 1) {
        if (threadIdx.x < off) {
            #pragma unroll
            for (int b = 0; b < BB; ++b)
                red[b][threadIdx.x] += red[b][threadIdx.x + off];
        }
        __syncthreads();
    }
    if (threadIdx.x < BB) {
        float sum = red[threadIdx.x][0] * (W_SCALE * W_SCALE) + EPSI;
        g_d[threadIdx.x * FO + fo] = rsqrtf(sum);
    }
}

// ---------------------------------------------------------------------------
// Kernel 4: xm = x*s, transposed to [b][r][c][fi], fp16
// ---------------------------------------------------------------------------
__global__ void k_xsplit(const float* __restrict__ x) {
    int b   = blockIdx.z;
    int r   = blockIdx.y;
    int fic = blockIdx.x * 64;
    __shared__ float tile[64][65];
    __shared__ float sv[64];
    int t = threadIdx.x;
    if (t < 64) sv[t] = g_s[b * FI + fic + t];
    #pragma unroll
    for (int i = 0; i < 16; ++i) {
        int idx = i * 256 + t;
        int fi = idx >> 6, c = idx & 63;
        tile[fi][c] = x[(((size_t)(b * FI + fic + fi)) * HH + r) * WW + c];
    }
    __syncthreads();
    #pragma unroll
    for (int i = 0; i < 16; ++i) {
        int idx = i * 256 + t;
        int c = idx >> 6, fi = idx & 63;
        float v = tile[fi][c] * sv[fi];
        size_t off = ((size_t)((b * HH + r) * WW + c) << 9) + fic + fi;
        g_xh[off] = __float2half(v);
    }
}

// ---------------------------------------------------------------------------
// Stage loader via cp.async:
//   A[128 px][80B rows, 64B data];  B[128 fo][80B rows, 64B data]
// ---------------------------------------------------------------------------
__device__ __forceinline__ void load_stage(int s, int b, int r0, int foB,
                                           uint32_t smA, int tid) {
    int kk = s >> 4;
    int fc = (s & 15) << 5;                 // fi chunk base (32 halves)
    int kd = kk / 3;
    int dr = kd - 1, dc = kk - kd * 3 - 1;
    uint32_t smB = smA + A_BYTES;
    // A: 512 transfers of 16B
    #pragma unroll
    for (int p = 0; p < 2; ++p) {
        int slot = p * 256 + tid;
        int row = slot >> 2, jj = slot & 3;
        int rr = r0 + (row >> 6) + dr;
        int cc = (row & 63) + dc;
        int ok  = ((unsigned)rr < (unsigned)HH) & ((unsigned)cc < (unsigned)WW);
        int off = ok ? ((((b * HH + rr) * WW + cc) << 9) + fc + jj * 8) : 0;
        cp16(smA + row * ROWB + jj * 16, g_xh + off, ok ? 16 : 0);
    }
    // B: 512 transfers of 16B
    #pragma unroll
    for (int p = 0; p < 2; ++p) {
        int slot = p * 256 + tid;
        int fo = slot >> 2, jj = slot & 3;
        int off = (foB + fo) * KTOT + (kk << 9) + fc + jj * 8;
        cp16(smB + fo * ROWB + jj * 16, g_wh + off, 16);
    }
}

// ---------------------------------------------------------------------------
// Kernel 5: implicit-GEMM conv on mma.sync (single term Ah*Bh, fp32 accum)
// CTA: M=128 px (2 rows x 64 cols), N=128 fo. 8 warps, warp tile 64x32.
// ---------------------------------------------------------------------------
__global__ void __launch_bounds__(256, 2)
k_conv_mma(float* __restrict__ y) {
    extern __shared__ char smem[];
    uint32_t sb = smem_u32(smem);
    const int tid = threadIdx.x;
    const int r0  = blockIdx.x * 2;
    const int foB = blockIdx.y * 128;
    const int b   = blockIdx.z;
    const int w   = tid >> 5, l = tid & 31;
    const int wm  = w >> 2, wn = w & 3;

    float acc[4][4][4];
    #pragma unroll
    for (int i = 0; i < 4; ++i)
        #pragma unroll
        for (int j = 0; j < 4; ++j)
            #pragma unroll
            for (int k = 0; k < 4; ++k) acc[i][j][k] = 0.f;

    // prologue: stages 0,1,2
    load_stage(0, b, r0, foB, sb, tid);                   CP_COMMIT();
    load_stage(1, b, r0, foB, sb + STAGE_BYTES, tid);     CP_COMMIT();
    load_stage(2, b, r0, foB, sb + 2 * STAGE_BYTES, tid); CP_COMMIT();

    // ldmatrix address components (80B rows, no swizzle)
    uint32_t aoff[4];
    #pragma unroll
    for (int am = 0; am < 4; ++am) {
        int rowA = wm * 64 + am * 16 + (l & 15);
        aoff[am] = (uint32_t)rowA * ROWB;
    }
    const uint32_t acol = ((l >> 4) & 1) * 16;
    uint32_t boff[2];
    #pragma unroll
    for (int bp = 0; bp < 2; ++bp) {
        int rowB = wn * 32 + bp * 16 + ((l >> 4) << 3) + (l & 7);
        boff[bp] = (uint32_t)A_BYTES + (uint32_t)rowB * ROWB;
    }
    const uint32_t bcol = ((l >> 3) & 1) * 16;

    for (int s = 0; s < NCHUNK; ++s) {
        CP_WAIT2();
        __syncthreads();
        if (s + 3 < NCHUNK)
            load_stage(s + 3, b, r0, foB,
                       sb + (uint32_t)((s + 3) % NSTG) * STAGE_BYTES, tid);
        CP_COMMIT();

        uint32_t st = sb + (uint32_t)(s % NSTG) * STAGE_BYTES;
        #pragma unroll
        for (int kst = 0; kst < 2; ++kst) {
            const uint32_t kb = (uint32_t)kst * 32;
            uint32_t ah[4][4], bh[2][4];
            #pragma unroll
            for (int bp = 0; bp < 2; ++bp)
                LDSM4(bh[bp], st + boff[bp] + bcol + kb);
            #pragma unroll
            for (int am = 0; am < 4; ++am)
                LDSM4(ah[am], st + aoff[am] + acol + kb);
            #pragma unroll
            for (int am = 0; am < 4; ++am)
                #pragma unroll
                for (int bn = 0; bn < 4; ++bn) {
                    int bp = bn >> 1, h = (bn & 1) * 2;
                    mma16816(acc[am][bn], ah[am], bh[bp][h], bh[bp][h + 1]);
                }
        }
    }

    // epilogue: apply demod, scatter to NCHW
    const float* dp = g_d + b * FO + foB;
    const int mlow = l >> 2;
    #pragma unroll
    for (int am = 0; am < 4; ++am) {
        int m0 = wm * 64 + am * 16 + mlow;
        int rr0 = r0 + (m0 >> 6), cc0 = m0 & 63;
        int m1 = m0 + 8;
        int rr1 = r0 + (m1 >> 6), cc1 = m1 & 63;
        #pragma unroll
        for (int bn = 0; bn < 4; ++bn) {
            int n = wn * 32 + bn * 8 + (l & 3) * 2;
            float d0 = dp[n], d1 = dp[n + 1];
            size_t base0 = ((size_t)((b * FO + foB + n)     * HH)) * WW;
            size_t base1 = ((size_t)((b * FO + foB + n + 1) * HH)) * WW;
            y[base0 + (size_t)rr0 * WW + cc0] = acc[am][bn][0] * d0;
            y[base1 + (size_t)rr0 * WW + cc0] = acc[am][bn][1] * d1;
            y[base0 + (size_t)rr1 * WW + cc1] = acc[am][bn][2] * d0;
            y[base1 + (size_t)rr1 * WW + cc1] = acc[am][bn][3] * d1;
        }
    }
}

// ---------------------------------------------------------------------------
extern "C" void kernel_launch(void* const* d_in, const int* in_sizes, int n_in,
                              void* d_out, int out_size) {
    const float* x     = (const float*)d_in[0];
    const float* style = (const float*)d_in[1];
    const float* w     = (const float*)d_in[2];
    const float* fc_w  = (const float*)d_in[3];
    const float* fc_b  = (const float*)d_in[4];
    float* y = (float*)d_out;

    static bool attr_set = false;
    if (!attr_set) {
        cudaFuncSetAttribute(k_conv_mma, cudaFuncAttributeMaxDynamicSharedMemorySize, SMEM_TOTAL);
        attr_set = true;
    }

    k_style<<<BB, 256>>>(style, fc_w, fc_b);
    k_wsplit<<<(FO * KTOT + 255) / 256, 256>>>(w);
    k_demod<<<FO, 256>>>(w);
    {
        dim3 g(FI / 64, HH, BB);   // (8, 64, 8)
        k_xsplit<<<g, 256>>>(x);
    }
    {
        dim3 g(HH / 2, FO / 128, BB);   // (32, 4, 8)
        k_conv_mma<<<g, 256, SMEM_TOTAL>>>(y);
    }
}

// round 12
// speedup vs baseline: 5.2309x; 1.0352x over previous
#include <cuda_runtime.h>
#include <cuda_fp16.h>
#include <cstdint>

// Problem constants
#define BB   8
#define FI   512
#define FO   512
#define HH   64
#define WW   64
#define DSTYLE 512
#define KTOT 4608                // 9 * 512

#define FC_SCALE 0.04419417382415922f      // 512^-0.5
#define W_SCALE  0.014731391274719739f     // (512*9)^-0.5
#define EPSI     1e-8f

// GEMM pipeline config
#define NSTG        5
#define ROWB        80           // 64B data + 16B pad -> conflict-free ldmatrix, no swizzle
#define A_BYTES     (128*ROWB)   // 10240
#define B_BYTES     (128*ROWB)   // 10240
#define STAGE_BYTES (A_BYTES + B_BYTES)        // 20480
#define SMEM_TOTAL  (NSTG*STAGE_BYTES)         // 102400 per CTA (2 CTAs/SM = 200KB)
#define NCHUNK      144          // 9 kk * 16 fi-chunks of 32

// Scratch (device globals; no allocation allowed)
__device__ float  g_s[BB*FI];
__device__ float  g_d[BB*FO];
__device__ __half g_wh[(size_t)FO*KTOT];     // w_hi  [fo][kk*512+fi]
__device__ __half g_xh[(size_t)BB*HH*WW*FI]; // xm_hi [b][r][c][fi]

// ---------------------------------------------------------------------------
// helpers
// ---------------------------------------------------------------------------
__device__ __forceinline__ uint32_t smem_u32(const void* p){
    uint32_t a;
    asm("{ .reg .u64 t; cvta.to.shared.u64 t, %1; cvt.u32.u64 %0, t; }"
        : "=r"(a) : "l"(p));
    return a;
}
__device__ __forceinline__ void cp16(uint32_t dst, const void* src, int srcsz){
    asm volatile("cp.async.cg.shared.global [%0], [%1], 16, %2;"
                 :: "r"(dst), "l"(src), "r"(srcsz) : "memory");
}
#define CP_COMMIT() asm volatile("cp.async.commit_group;" ::: "memory")
#define CP_WAIT3()  asm volatile("cp.async.wait_group 3;" ::: "memory")

#define LDSM4(r, addr) \
    asm volatile("ldmatrix.sync.aligned.m8n8.x4.shared.b16 {%0,%1,%2,%3}, [%4];" \
        : "=r"((r)[0]),"=r"((r)[1]),"=r"((r)[2]),"=r"((r)[3]) : "r"(addr))

__device__ __forceinline__ void mma16816(float* c, const uint32_t* a,
                                         uint32_t b0, uint32_t b1){
    asm volatile("mma.sync.aligned.m16n8k16.row.col.f32.f16.f16.f32 "
        "{%0,%1,%2,%3}, {%4,%5,%6,%7}, {%8,%9}, {%0,%1,%2,%3};"
        : "+f"(c[0]),"+f"(c[1]),"+f"(c[2]),"+f"(c[3])
        : "r"(a[0]),"r"(a[1]),"r"(a[2]),"r"(a[3]), "r"(b0),"r"(b1));
}

// ---------------------------------------------------------------------------
// Kernel 1: s[b,i] = fc_b[i] + fc_scale * sum_j style[b,j] * fc_w[i,j]
// ---------------------------------------------------------------------------
__global__ void k_style(const float* __restrict__ style,
                        const float* __restrict__ fc_w,
                        const float* __restrict__ fc_b) {
    int b = blockIdx.x;
    __shared__ float st[DSTYLE];
    for (int j = threadIdx.x; j < DSTYLE; j += blockDim.x)
        st[j] = style[b * DSTYLE + j];
    __syncthreads();
    for (int i = threadIdx.x; i < FI; i += blockDim.x) {
        const float* wr = fc_w + (size_t)i * DSTYLE;
        float acc = 0.f;
        #pragma unroll 8
        for (int j = 0; j < DSTYLE; ++j) acc += st[j] * wr[j];
        g_s[b * FI + i] = acc * FC_SCALE + fc_b[i];
    }
}

// ---------------------------------------------------------------------------
// Kernel 2: fp16 of scaled weights, reordered to [fo][kk*512+fi]
// ---------------------------------------------------------------------------
__global__ void k_wsplit(const float* __restrict__ w) {
    int idx = blockIdx.x * blockDim.x + threadIdx.x;
    if (idx >= FO * KTOT) return;
    int fo  = idx / KTOT;
    int rem = idx - fo * KTOT;
    int kk  = rem >> 9;
    int fi  = rem & 511;
    float v = w[((size_t)(fo * FI + fi)) * 9 + kk] * W_SCALE;
    g_wh[idx] = __float2half(v);
}

// ---------------------------------------------------------------------------
// Kernel 3: d[b,fo] = rsqrt( ws^2 * sum_fi (sum_k w^2) * s[b,fi]^2 + eps )
// ---------------------------------------------------------------------------
__global__ void k_demod(const float* __restrict__ w) {
    int fo = blockIdx.x;
    float p[BB];
    #pragma unroll
    for (int b = 0; b < BB; ++b) p[b] = 0.f;
    for (int fi = threadIdx.x; fi < FI; fi += blockDim.x) {
        const float* wp = w + ((size_t)fo * FI + fi) * 9;
        float wsq = 0.f;
        #pragma unroll
        for (int k = 0; k < 9; ++k) { float v = wp[k]; wsq += v * v; }
        #pragma unroll
        for (int b = 0; b < BB; ++b) {
            float sv = g_s[b * FI + fi];
            p[b] += wsq * sv * sv;
        }
    }
    __shared__ float red[BB][256];
    #pragma unroll
    for (int b = 0; b < BB; ++b) red[b][threadIdx.x] = p[b];
    __syncthreads();
    for (int off = 128; off > 0; off >>= 1) {
        if (threadIdx.x < off) {
            #pragma unroll
            for (int b = 0; b < BB; ++b)
                red[b][threadIdx.x] += red[b][threadIdx.x + off];
        }
        __syncthreads();
    }
    if (threadIdx.x < BB) {
        float sum = red[threadIdx.x][0] * (W_SCALE * W_SCALE) + EPSI;
        g_d[threadIdx.x * FO + fo] = rsqrtf(sum);
    }
}

// ---------------------------------------------------------------------------
// Kernel 4: xm = x*s, transposed to [b][r][c][fi], fp16
// ---------------------------------------------------------------------------
__global__ void k_xsplit(const float* __restrict__ x) {
    int b   = blockIdx.z;
    int r   = blockIdx.y;
    int fic = blockIdx.x * 64;
    __shared__ float tile[64][65];
    __shared__ float sv[64];
    int t = threadIdx.x;
    if (t < 64) sv[t] = g_s[b * FI + fic + t];
    #pragma unroll
    for (int i = 0; i < 16; ++i) {
        int idx = i * 256 + t;
        int fi = idx >> 6, c = idx & 63;
        tile[fi][c] = x[(((size_t)(b * FI + fic + fi)) * HH + r) * WW + c];
    }
    __syncthreads();
    #pragma unroll
    for (int i = 0; i < 16; ++i) {
        int idx = i * 256 + t;
        int c = idx >> 6, fi = idx & 63;
        float v = tile[fi][c] * sv[fi];
        size_t off = ((size_t)((b * HH + r) * WW + c) << 9) + fic + fi;
        g_xh[off] = __float2half(v);
    }
}

// ---------------------------------------------------------------------------
// Stage loader via cp.async (128 threads):
//   A[128 px][80B rows, 64B data];  B[128 fo][80B rows, 64B data]
// ---------------------------------------------------------------------------
__device__ __forceinline__ void load_stage(int s, int b, int r0, int foB,
                                           uint32_t smA, int tid) {
    int kk = s >> 4;
    int fc = (s & 15) << 5;                 // fi chunk base within kk
    int kd = kk / 3;
    int dr = kd - 1, dc = kk - kd * 3 - 1;
    uint32_t smB = smA + A_BYTES;
    const int kofsB = s << 5;               // kk*512 + fc == 32*s
    // A: 512 transfers of 16B, 4 per thread
    #pragma unroll
    for (int p = 0; p < 4; ++p) {
        int slot = p * 128 + tid;
        int row = slot >> 2, jj = slot & 3;
        int rr = r0 + (row >> 6) + dr;
        int cc = (row & 63) + dc;
        int ok  = ((unsigned)rr < (unsigned)HH) & ((unsigned)cc < (unsigned)WW);
        int off = ok ? ((((b * HH + rr) * WW + cc) << 9) + fc + jj * 8) : 0;
        cp16(smA + row * ROWB + jj * 16, g_xh + off, ok ? 16 : 0);
    }
    // B: 512 transfers of 16B, 4 per thread
    #pragma unroll
    for (int p = 0; p < 4; ++p) {
        int slot = p * 128 + tid;
        int fo = slot >> 2, jj = slot & 3;
        int off = (foB + fo) * KTOT + kofsB + jj * 8;
        cp16(smB + fo * ROWB + jj * 16, g_wh + off, 16);
    }
}

// ---------------------------------------------------------------------------
// Kernel 5: implicit-GEMM conv on mma.sync (single term, fp32 accum)
// CTA: M=128 px, N=128 fo; 4 warps, warp tile 64x64; 2 CTAs/SM; 5 stages.
// ---------------------------------------------------------------------------
__global__ void __launch_bounds__(128, 2)
k_conv_mma(float* __restrict__ y) {
    extern __shared__ char smem[];
    uint32_t sb = smem_u32(smem);
    const int tid = threadIdx.x;
    const int r0  = blockIdx.x * 2;
    const int foB = blockIdx.y * 128;
    const int b   = blockIdx.z;
    const int w   = tid >> 5, l = tid & 31;
    const int wm  = w & 1, wn = w >> 1;     // 2x2 warp grid, tile 64x64

    float acc[4][8][4];
    #pragma unroll
    for (int i = 0; i < 4; ++i)
        #pragma unroll
        for (int j = 0; j < 8; ++j)
            #pragma unroll
            for (int k = 0; k < 4; ++k) acc[i][j][k] = 0.f;

    // prologue: stages 0..3
    load_stage(0, b, r0, foB, sb, tid);                   CP_COMMIT();
    load_stage(1, b, r0, foB, sb + STAGE_BYTES, tid);     CP_COMMIT();
    load_stage(2, b, r0, foB, sb + 2 * STAGE_BYTES, tid); CP_COMMIT();
    load_stage(3, b, r0, foB, sb + 3 * STAGE_BYTES, tid); CP_COMMIT();

    // ldmatrix address components (80B rows, no swizzle)
    uint32_t aoff[4];
    #pragma unroll
    for (int am = 0; am < 4; ++am) {
        int rowA = wm * 64 + am * 16 + (l & 15);
        aoff[am] = (uint32_t)rowA * ROWB;
    }
    const uint32_t acol = ((l >> 4) & 1) * 16;
    uint32_t boff[4];
    #pragma unroll
    for (int bp = 0; bp < 4; ++bp) {
        int rowB = wn * 64 + bp * 16 + ((l >> 4) << 3) + (l & 7);
        boff[bp] = (uint32_t)A_BYTES + (uint32_t)rowB * ROWB;
    }
    const uint32_t bcol = ((l >> 3) & 1) * 16;

    for (int s = 0; s < NCHUNK; ++s) {
        CP_WAIT3();
        __syncthreads();
        if (s + 4 < NCHUNK)
            load_stage(s + 4, b, r0, foB,
                       sb + (uint32_t)((s + 4) % NSTG) * STAGE_BYTES, tid);
        CP_COMMIT();

        uint32_t st = sb + (uint32_t)(s % NSTG) * STAGE_BYTES;
        #pragma unroll
        for (int kst = 0; kst < 2; ++kst) {
            const uint32_t kb = (uint32_t)kst * 32;
            uint32_t ah[4][4], bh[4][4];
            #pragma unroll
            for (int bp = 0; bp < 4; ++bp)
                LDSM4(bh[bp], st + boff[bp] + bcol + kb);
            #pragma unroll
            for (int am = 0; am < 4; ++am)
                LDSM4(ah[am], st + aoff[am] + acol + kb);
            #pragma unroll
            for (int am = 0; am < 4; ++am)
                #pragma unroll
                for (int bn = 0; bn < 8; ++bn) {
                    int bp = bn >> 1, h = (bn & 1) * 2;
                    mma16816(acc[am][bn], ah[am], bh[bp][h], bh[bp][h + 1]);
                }
        }
    }

    // epilogue: apply demod, scatter to NCHW
    const float* dp = g_d + b * FO + foB;
    const int mlow = l >> 2;
    #pragma unroll
    for (int am = 0; am < 4; ++am) {
        int m0 = wm * 64 + am * 16 + mlow;
        int rr0 = r0 + (m0 >> 6), cc0 = m0 & 63;
        int m1 = m0 + 8;
        int rr1 = r0 + (m1 >> 6), cc1 = m1 & 63;
        #pragma unroll
        for (int bn = 0; bn < 8; ++bn) {
            int n = wn * 64 + bn * 8 + (l & 3) * 2;
            float d0 = dp[n], d1 = dp[n + 1];
            size_t base0 = ((size_t)((b * FO + foB + n)     * HH)) * WW;
            size_t base1 = ((size_t)((b * FO + foB + n + 1) * HH)) * WW;
            y[base0 + (size_t)rr0 * WW + cc0] = acc[am][bn][0] * d0;
            y[base1 + (size_t)rr0 * WW + cc0] = acc[am][bn][1] * d1;
            y[base0 + (size_t)rr1 * WW + cc1] = acc[am][bn][2] * d0;
            y[base1 + (size_t)rr1 * WW + cc1] = acc[am][bn][3] * d1;
        }
    }
}

// ---------------------------------------------------------------------------
extern "C" void kernel_launch(void* const* d_in, const int* in_sizes, int n_in,
                              void* d_out, int out_size) {
    const float* x     = (const float*)d_in[0];
    const float* style = (const float*)d_in[1];
    const float* w     = (const float*)d_in[2];
    const float* fc_w  = (const float*)d_in[3];
    const float* fc_b  = (const float*)d_in[4];
    float* y = (float*)d_out;

    static bool attr_set = false;
    if (!attr_set) {
        cudaFuncSetAttribute(k_conv_mma, cudaFuncAttributeMaxDynamicSharedMemorySize, SMEM_TOTAL);
        attr_set = true;
    }

    k_style<<<BB, 256>>>(style, fc_w, fc_b);
    k_wsplit<<<(FO * KTOT + 255) / 256, 256>>>(w);
    k_demod<<<FO, 256>>>(w);
    {
        dim3 g(FI / 64, HH, BB);   // (8, 64, 8)
        k_xsplit<<<g, 256>>>(x);
    }
    {
        dim3 g(HH / 2, FO / 128, BB);   // (32, 4, 8)
        k_conv_mma<<<g, 128, SMEM_TOTAL>>>(y);
    }
}

// round 13
// speedup vs baseline: 5.2930x; 1.0119x over previous
#include <cuda_runtime.h>
#include <cuda_fp16.h>
#include <cstdint>

// Problem constants
#define BB   8
#define FI   512
#define FO   512
#define HH   64
#define WW   64
#define DSTYLE 512
#define KTOT 4608                // 9 * 512

#define FC_SCALE 0.04419417382415922f      // 512^-0.5
#define W_SCALE  0.014731391274719739f     // (512*9)^-0.5
#define EPSI     1e-8f

// GEMM pipeline config
#define NSTG        5
#define ROWB        80           // 64B data + 16B pad -> conflict-free ldmatrix, no swizzle
#define A_BYTES     (128*ROWB)   // 10240
#define B_BYTES     (128*ROWB)   // 10240
#define STAGE_BYTES (A_BYTES + B_BYTES)        // 20480
#define SMEM_TOTAL  (NSTG*STAGE_BYTES)         // 102400 per CTA (2 CTAs/SM)
#define NCHUNK      144          // 9 kk * 16 fi-chunks of 32

// Scratch (device globals; no allocation allowed)
__device__ float  g_s[BB*FI];
__device__ float  g_d[BB*FO];
__device__ __half g_wh[(size_t)FO*KTOT];     // w_hi  [fo][kk*512+fi]
__device__ __half g_xh[(size_t)BB*HH*WW*FI]; // xm_hi [b][r][c][fi]

// ---------------------------------------------------------------------------
// helpers
// ---------------------------------------------------------------------------
__device__ __forceinline__ uint32_t smem_u32(const void* p){
    uint32_t a;
    asm("{ .reg .u64 t; cvta.to.shared.u64 t, %1; cvt.u32.u64 %0, t; }"
        : "=r"(a) : "l"(p));
    return a;
}
__device__ __forceinline__ void cp16(uint32_t dst, const void* src, int srcsz){
    asm volatile("cp.async.cg.shared.global [%0], [%1], 16, %2;"
                 :: "r"(dst), "l"(src), "r"(srcsz) : "memory");
}
#define CP_COMMIT() asm volatile("cp.async.commit_group;" ::: "memory")
#define CP_WAIT3()  asm volatile("cp.async.wait_group 3;" ::: "memory")

#define LDSM4(r, addr) \
    asm volatile("ldmatrix.sync.aligned.m8n8.x4.shared.b16 {%0,%1,%2,%3}, [%4];" \
        : "=r"((r)[0]),"=r"((r)[1]),"=r"((r)[2]),"=r"((r)[3]) : "r"(addr))

__device__ __forceinline__ void mma16816(float* c, const uint32_t* a,
                                         uint32_t b0, uint32_t b1){
    asm volatile("mma.sync.aligned.m16n8k16.row.col.f32.f16.f16.f32 "
        "{%0,%1,%2,%3}, {%4,%5,%6,%7}, {%8,%9}, {%0,%1,%2,%3};"
        : "+f"(c[0]),"+f"(c[1]),"+f"(c[2]),"+f"(c[3])
        : "r"(a[0]),"r"(a[1]),"r"(a[2]),"r"(a[3]), "r"(b0),"r"(b1));
}

// ---------------------------------------------------------------------------
// Kernel 1: s[b,i] = fc_b[i] + fc_scale * sum_j style[b,j] * fc_w[i,j]
// ---------------------------------------------------------------------------
__global__ void k_style(const float* __restrict__ style,
                        const float* __restrict__ fc_w,
                        const float* __restrict__ fc_b) {
    int b = blockIdx.x;
    __shared__ float st[DSTYLE];
    for (int j = threadIdx.x; j < DSTYLE; j += blockDim.x)
        st[j] = style[b * DSTYLE + j];
    __syncthreads();
    for (int i = threadIdx.x; i < FI; i += blockDim.x) {
        const float* wr = fc_w + (size_t)i * DSTYLE;
        float acc = 0.f;
        #pragma unroll 8
        for (int j = 0; j < DSTYLE; ++j) acc += st[j] * wr[j];
        g_s[b * FI + i] = acc * FC_SCALE + fc_b[i];
    }
}

// ---------------------------------------------------------------------------
// Kernel 2: fp16 of scaled weights, reordered to [fo][kk*512+fi].
// One fo per block; stage the 4608-float row through smem so both the
// global read and the global write are fully coalesced.
// ---------------------------------------------------------------------------
__global__ void k_wsplit(const float* __restrict__ w) {
    __shared__ float row[KTOT / FI * FI];    // 4608 floats
    int fo = blockIdx.x;
    const float* src = w + (size_t)fo * KTOT;
    for (int i = threadIdx.x; i < KTOT; i += blockDim.x)
        row[i] = src[i];
    __syncthreads();
    __half* dst = g_wh + (size_t)fo * KTOT;
    for (int i = threadIdx.x; i < KTOT; i += blockDim.x) {
        int kk = i >> 9, fi = i & 511;       // dst index: kk*512+fi
        dst[i] = __float2half(row[fi * 9 + kk] * W_SCALE);  // stride-9: bank-conflict-free
    }
}

// ---------------------------------------------------------------------------
// Kernel 3: d[b,fo] = rsqrt( ws^2 * sum_fi (sum_k w^2) * s[b,fi]^2 + eps )
// ---------------------------------------------------------------------------
__global__ void k_demod(const float* __restrict__ w) {
    int fo = blockIdx.x;
    float p[BB];
    #pragma unroll
    for (int b = 0; b < BB; ++b) p[b] = 0.f;
    for (int fi = threadIdx.x; fi < FI; fi += blockDim.x) {
        const float* wp = w + ((size_t)fo * FI + fi) * 9;
        float wsq = 0.f;
        #pragma unroll
        for (int k = 0; k < 9; ++k) { float v = wp[k]; wsq += v * v; }
        #pragma unroll
        for (int b = 0; b < BB; ++b) {
            float sv = g_s[b * FI + fi];
            p[b] += wsq * sv * sv;
        }
    }
    __shared__ float red[BB][256];
    #pragma unroll
    for (int b = 0; b < BB; ++b) red[b][threadIdx.x] = p[b];
    __syncthreads();
    for (int off = 128; off > 0; off >>= 1) {
        if (threadIdx.x < off) {
            #pragma unroll
            for (int b = 0; b < BB; ++b)
                red[b][threadIdx.x] += red[b][threadIdx.x + off];
        }
        __syncthreads();
    }
    if (threadIdx.x < BB) {
        float sum = red[threadIdx.x][0] * (W_SCALE * W_SCALE) + EPSI;
        g_d[threadIdx.x * FO + fo] = rsqrtf(sum);
    }
}

// ---------------------------------------------------------------------------
// Kernel 4: xm = x*s, transposed to [b][r][c][fi], fp16 (half2 stores)
// ---------------------------------------------------------------------------
__global__ void k_xsplit(const float* __restrict__ x) {
    int b   = blockIdx.z;
    int r   = blockIdx.y;
    int fic = blockIdx.x * 64;
    __shared__ float tile[64][65];
    __shared__ float sv[64];
    int t = threadIdx.x;
    if (t < 64) sv[t] = g_s[b * FI + fic + t];
    #pragma unroll
    for (int i = 0; i < 16; ++i) {
        int idx = i * 256 + t;
        int fi = idx >> 6, c = idx & 63;
        tile[fi][c] = x[(((size_t)(b * FI + fic + fi)) * HH + r) * WW + c];
    }
    __syncthreads();
    // 64 c x 32 half2-slots; consecutive threads -> consecutive fi pairs
    __half2* outp = (__half2*)(g_xh + (((size_t)((b * HH + r) * WW)) << 9) + fic);
    #pragma unroll
    for (int i = 0; i < 8; ++i) {
        int idx = i * 256 + t;
        int c = idx >> 5, f2 = idx & 31;
        int fi = f2 * 2;
        float v0 = tile[fi][c]     * sv[fi];
        float v1 = tile[fi + 1][c] * sv[fi + 1];
        outp[(size_t)c * 256 + f2] = __floats2half2_rn(v0, v1);
    }
}

// ---------------------------------------------------------------------------
// Stage loader via cp.async (128 threads), hoisted per-thread bases:
//   A[128 px][80B rows, 64B data];  B[128 fo][80B rows, 64B data]
// ---------------------------------------------------------------------------
struct LoaderCtx {
    // A side (4 slots/thread): per-slot precomputed
    int rrA[4], ccA[4];              // un-shifted pixel coords
    const __half* srcA[4];           // g_xh + pixbase + jj*8
    uint32_t dstA[4];                // smem offset within stage
    // B side (4 slots/thread)
    const __half* srcB[4];           // advances 32 halves per chunk
    uint32_t dstB[4];
};

__device__ __forceinline__ void loader_init(LoaderCtx& L, int tid, int b,
                                            int r0, int foB) {
    #pragma unroll
    for (int p = 0; p < 4; ++p) {
        int slot = p * 128 + tid;
        int row = slot >> 2, jj = slot & 3;
        int rr = r0 + (row >> 6);
        int cc = row & 63;
        L.rrA[p] = rr; L.ccA[p] = cc;
        L.srcA[p] = g_xh + (((size_t)((b * HH + rr) * WW + cc)) << 9) + jj * 8;
        L.dstA[p] = (uint32_t)row * ROWB + jj * 16;
        int fo = row;
        L.srcB[p] = g_wh + (size_t)(foB + fo) * KTOT + jj * 8;
        L.dstB[p] = (uint32_t)A_BYTES + (uint32_t)fo * ROWB + jj * 16;
    }
}

__device__ __forceinline__ void load_stage(const LoaderCtx& L, int s, uint32_t smA) {
    int kk = s >> 4;
    int fc = (s & 15) << 5;
    int kd = kk / 3;
    int dr = kd - 1, dc = kk - kd * 3 - 1;
    const int adel = ((dr * WW + dc) << 9) + fc;   // A source delta (halves)
    const int bdel = s << 5;                        // B source delta (halves)
    #pragma unroll
    for (int p = 0; p < 4; ++p) {
        int rr = L.rrA[p] + dr, cc = L.ccA[p] + dc;
        int ok = ((unsigned)rr < (unsigned)HH) & ((unsigned)cc < (unsigned)WW);
        const __half* src = L.srcA[p] + (ok ? adel : -(int)( (((size_t)((L.rrA[p]*0)))) ) - ( (int)((L.srcA[p] - g_xh)) ));
        // when !ok, point at g_xh[0] (valid) and request 0 bytes
        cp16(smA + L.dstA[p], ok ? (const void*)(L.srcA[p] + adel) : (const void*)g_xh,
             ok ? 16 : 0);
        (void)src;
    }
    #pragma unroll
    for (int p = 0; p < 4; ++p)
        cp16(smA + L.dstB[p], L.srcB[p] + bdel, 16);
}

// ---------------------------------------------------------------------------
// Kernel 5: implicit-GEMM conv on mma.sync (single term, fp32 accum)
// CTA: M=128 px, N=128 fo; 4 warps, warp tile 64x64; 2 CTAs/SM; 5 stages.
// ---------------------------------------------------------------------------
__global__ void __launch_bounds__(128, 2)
k_conv_mma(float* __restrict__ y) {
    extern __shared__ char smem[];
    uint32_t sb = smem_u32(smem);
    const int tid = threadIdx.x;
    const int r0  = blockIdx.x * 2;
    const int foB = blockIdx.y * 128;
    const int b   = blockIdx.z;
    const int w   = tid >> 5, l = tid & 31;
    const int wm  = w & 1, wn = w >> 1;     // 2x2 warp grid, tile 64x64

    float acc[4][8][4];
    #pragma unroll
    for (int i = 0; i < 4; ++i)
        #pragma unroll
        for (int j = 0; j < 8; ++j)
            #pragma unroll
            for (int k = 0; k < 4; ++k) acc[i][j][k] = 0.f;

    LoaderCtx L;
    loader_init(L, tid, b, r0, foB);

    // prologue: stages 0..3
    load_stage(L, 0, sb);                   CP_COMMIT();
    load_stage(L, 1, sb + STAGE_BYTES);     CP_COMMIT();
    load_stage(L, 2, sb + 2 * STAGE_BYTES); CP_COMMIT();
    load_stage(L, 3, sb + 3 * STAGE_BYTES); CP_COMMIT();

    // ldmatrix address components (80B rows, no swizzle)
    uint32_t aoff[4];
    #pragma unroll
    for (int am = 0; am < 4; ++am) {
        int rowA = wm * 64 + am * 16 + (l & 15);
        aoff[am] = (uint32_t)rowA * ROWB;
    }
    const uint32_t acol = ((l >> 4) & 1) * 16;
    uint32_t boff[4];
    #pragma unroll
    for (int bp = 0; bp < 4; ++bp) {
        int rowB = wn * 64 + bp * 16 + ((l >> 4) << 3) + (l & 7);
        boff[bp] = (uint32_t)A_BYTES + (uint32_t)rowB * ROWB;
    }
    const uint32_t bcol = ((l >> 3) & 1) * 16;

    for (int s = 0; s < NCHUNK; ++s) {
        CP_WAIT3();
        __syncthreads();
        if (s + 4 < NCHUNK)
            load_stage(L, s + 4, sb + (uint32_t)((s + 4) % NSTG) * STAGE_BYTES);
        CP_COMMIT();

        uint32_t st = sb + (uint32_t)(s % NSTG) * STAGE_BYTES;
        // preload ALL fragments for both kst, then one long MMA runway
        uint32_t ah[2][4][4], bh[2][4][4];
        #pragma unroll
        for (int kst = 0; kst < 2; ++kst) {
            const uint32_t kb = (uint32_t)kst * 32;
            #pragma unroll
            for (int bp = 0; bp < 4; ++bp)
                LDSM4(bh[kst][bp], st + boff[bp] + bcol + kb);
            #pragma unroll
            for (int am = 0; am < 4; ++am)
                LDSM4(ah[kst][am], st + aoff[am] + acol + kb);
        }
        #pragma unroll
        for (int kst = 0; kst < 2; ++kst)
            #pragma unroll
            for (int am = 0; am < 4; ++am)
                #pragma unroll
                for (int bn = 0; bn < 8; ++bn) {
                    int bp = bn >> 1, h = (bn & 1) * 2;
                    mma16816(acc[am][bn], ah[kst][am], bh[kst][bp][h], bh[kst][bp][h + 1]);
                }
    }

    // epilogue: apply demod, scatter to NCHW (32B-sector efficient)
    const float* dp = g_d + b * FO + foB;
    const int mlow = l >> 2;
    #pragma unroll
    for (int am = 0; am < 4; ++am) {
        int m0 = wm * 64 + am * 16 + mlow;
        int rr0 = r0 + (m0 >> 6), cc0 = m0 & 63;
        int m1 = m0 + 8;
        int rr1 = r0 + (m1 >> 6), cc1 = m1 & 63;
        #pragma unroll
        for (int bn = 0; bn < 8; ++bn) {
            int n = wn * 64 + bn * 8 + (l & 3) * 2;
            float d0 = dp[n], d1 = dp[n + 1];
            size_t base0 = ((size_t)((b * FO + foB + n)     * HH)) * WW;
            size_t base1 = ((size_t)((b * FO + foB + n + 1) * HH)) * WW;
            y[base0 + (size_t)rr0 * WW + cc0] = acc[am][bn][0] * d0;
            y[base1 + (size_t)rr0 * WW + cc0] = acc[am][bn][1] * d1;
            y[base0 + (size_t)rr1 * WW + cc1] = acc[am][bn][2] * d0;
            y[base1 + (size_t)rr1 * WW + cc1] = acc[am][bn][3] * d1;
        }
    }
}

// ---------------------------------------------------------------------------
extern "C" void kernel_launch(void* const* d_in, const int* in_sizes, int n_in,
                              void* d_out, int out_size) {
    const float* x     = (const float*)d_in[0];
    const float* style = (const float*)d_in[1];
    const float* w     = (const float*)d_in[2];
    const float* fc_w  = (const float*)d_in[3];
    const float* fc_b  = (const float*)d_in[4];
    float* y = (float*)d_out;

    static bool attr_set = false;
    if (!attr_set) {
        cudaFuncSetAttribute(k_conv_mma, cudaFuncAttributeMaxDynamicSharedMemorySize, SMEM_TOTAL);
        attr_set = true;
    }

    k_style<<<BB, 256>>>(style, fc_w, fc_b);
    k_wsplit<<<FO, 256>>>(w);
    k_demod<<<FO, 256>>>(w);
    {
        dim3 g(FI / 64, HH, BB);   // (8, 64, 8)
        k_xsplit<<<g, 256>>>(x);
    }
    {
        dim3 g(HH / 2, FO / 128, BB);   // (32, 4, 8)
        k_conv_mma<<<g, 128, SMEM_TOTAL>>>(y);
    }
}